// round 15
// baseline (speedup 1.0000x reference)
#include <cuda_runtime.h>
#include <cstdint>

#define N_Q 1024
#define N_O 2048
#define LATENT 128
#define HEADS 4
#define SEGS 9
#define O_TILE 32
// tiles: 64 total; segs 0..7 get 7 tiles, seg 8 gets 8

#define BO_BYTES 16896                                  // 32 rows x 33 ulonglong2 (padded, transposed)
#define V_BYTES 16384
#define WP_OFF (2 * BO_BYTES + 2 * V_BYTES)             // 66560
#define DYN_BYTES (WP_OFF + 8 * 16 * 36 * 4)            // 66560 + 18432 = 84992

typedef unsigned long long ull;

// ---------------- scratch (static device globals; no allocation) ----------------
__device__ float g_v[N_O * LATENT];
__device__ float g_bo[N_O * LATENT];
__device__ float g_aq[N_Q * LATENT];
__device__ float g_s2[SEGS * N_Q * HEADS];              // per-segment exp-sums
__device__ float g_acc[SEGS * N_Q * LATENT];            // per-segment weighted partials

// ---------------- packed f32x2 helpers ----------------
__device__ __forceinline__ ull fma2(ull a, ull b, ull c) {
    ull d; asm("fma.rn.f32x2 %0, %1, %2, %3;" : "=l"(d) : "l"(a), "l"(b), "l"(c)); return d;
}
__device__ __forceinline__ ull add2(ull a, ull b) {
    ull d; asm("add.rn.f32x2 %0, %1, %2;" : "=l"(d) : "l"(a), "l"(b)); return d;
}
__device__ __forceinline__ ull relu2(ull a) {
    ull d;
    asm("{\n\t"
        ".reg .f32 lo, hi;\n\t"
        "mov.b64 {lo, hi}, %1;\n\t"
        "max.f32 lo, lo, 0f00000000;\n\t"
        "max.f32 hi, hi, 0f00000000;\n\t"
        "mov.b64 %0, {lo, hi};\n\t"
        "}" : "=l"(d) : "l"(a));
    return d;
}
__device__ __forceinline__ ull pack2(float x, float y) {
    ull d; asm("mov.b64 %0, {%1, %2};" : "=l"(d) : "f"(x), "f"(y)); return d;
}
__device__ __forceinline__ float2 unpack2(ull a) {
    float2 f; asm("mov.b64 {%0, %1}, %2;" : "=f"(f.x), "=f"(f.y) : "l"(a)); return f;
}
__device__ __forceinline__ void cpasync16(unsigned int saddr, const void* gaddr) {
    asm volatile("cp.async.cg.shared.global [%0], [%1], 16;" :: "r"(saddr), "l"(gaddr));
}
__device__ __forceinline__ float fsqrt_approx(float x) {
    float r; asm("sqrt.approx.f32 %0, %1;" : "=f"(r) : "f"(x)); return r;
}

// ---------------- kernel 1: precompute ----------------
// Blocks 0..63: obs (block = 32 obs; warp = 4 obs; Wv loads amortized over 4 obs).
// Blocks 64..95: queries (block = 32 q).
__global__ __launch_bounds__(256) void pre_kernel(
    const float* __restrict__ h_obs,
    const float* __restrict__ pos_obs,
    const float* __restrict__ pos_query,
    const float* __restrict__ W1,
    const float* __restrict__ b1,
    const float* __restrict__ ln_gamma,
    const float* __restrict__ ln_beta,
    const float* __restrict__ Wv,
    const float* __restrict__ bv) {

    if (blockIdx.x < 64) {
        __shared__ float s_hn[8][4][LATENT];              // [warp][obs][latent]  16 KB
        int warp = threadIdx.x >> 5, lane = threadIdx.x & 31;
        int o0 = blockIdx.x * 32 + warp * 4;

        const float4* h4p = (const float4*)h_obs;
        const float4* W14 = (const float4*)W1;
        float4 gam = ((const float4*)ln_gamma)[lane];
        float4 bet = ((const float4*)ln_beta)[lane];

        // bo weights hoisted
        float4 bw0, bw1, bw2;
        {
            float4 a3 = W14[3 * 32 + lane], a4 = W14[4 * 32 + lane], a5 = W14[5 * 32 + lane];
            float4 a6 = W14[6 * 32 + lane], a7 = W14[7 * 32 + lane], a8 = W14[8 * 32 + lane];
            bw0.x = a3.x - a6.x; bw0.y = a3.y - a6.y; bw0.z = a3.z - a6.z; bw0.w = a3.w - a6.w;
            bw1.x = a4.x - a7.x; bw1.y = a4.y - a7.y; bw1.z = a4.z - a7.z; bw1.w = a4.w - a7.w;
            bw2.x = a5.x - a8.x; bw2.y = a5.y - a8.y; bw2.z = a5.z - a8.z; bw2.w = a5.w - a8.w;
        }

        #pragma unroll
        for (int oi = 0; oi < 4; oi++) {
            int o = o0 + oi;
            float4 h = h4p[o * 32 + lane];
            float s1 = h.x + h.y + h.z + h.w;
            float s2 = h.x * h.x + h.y * h.y + h.z * h.z + h.w * h.w;
            #pragma unroll
            for (int off = 16; off; off >>= 1) {
                s1 += __shfl_xor_sync(0xffffffffu, s1, off);
                s2 += __shfl_xor_sync(0xffffffffu, s2, off);
            }
            float mu = s1 * (1.0f / LATENT);
            float var = s2 * (1.0f / LATENT) - mu * mu;
            float rs = rsqrtf(var + 1e-5f);
            float4 hn;
            hn.x = (h.x - mu) * rs * gam.x + bet.x;
            hn.y = (h.y - mu) * rs * gam.y + bet.y;
            hn.z = (h.z - mu) * rs * gam.z + bet.z;
            hn.w = (h.w - mu) * rs * gam.w + bet.w;
            ((float4*)s_hn[warp][oi])[lane] = hn;

            float p0 = pos_obs[o * 3 + 0], p1 = pos_obs[o * 3 + 1], p2 = pos_obs[o * 3 + 2];
            float4 bo;
            bo.x = p0 * bw0.x + p1 * bw1.x + p2 * bw2.x;
            bo.y = p0 * bw0.y + p1 * bw1.y + p2 * bw2.y;
            bo.z = p0 * bw0.z + p1 * bw1.z + p2 * bw2.z;
            bo.w = p0 * bw0.w + p1 * bw1.w + p2 * bw2.w;
            ((float4*)g_bo)[o * 32 + lane] = bo;
        }
        __syncwarp();

        // v = hn @ Wv + bv for 4 obs (Wv loaded once per k-quad)
        float4 acc[4];
        float4 bvv = ((const float4*)bv)[lane];
        #pragma unroll
        for (int oi = 0; oi < 4; oi++) acc[oi] = bvv;

        const float4* wv4 = (const float4*)Wv;
        #pragma unroll 2
        for (int k4 = 0; k4 < 32; k4++) {
            float4 wv0 = wv4[(k4 * 4 + 0) * 32 + lane];
            float4 wv1 = wv4[(k4 * 4 + 1) * 32 + lane];
            float4 wv2 = wv4[(k4 * 4 + 2) * 32 + lane];
            float4 wv3 = wv4[(k4 * 4 + 3) * 32 + lane];
            #pragma unroll
            for (int oi = 0; oi < 4; oi++) {
                float4 hk = ((const float4*)s_hn[warp][oi])[k4];   // broadcast LDS.128
                acc[oi].x += hk.x * wv0.x; acc[oi].y += hk.x * wv0.y;
                acc[oi].z += hk.x * wv0.z; acc[oi].w += hk.x * wv0.w;
                acc[oi].x += hk.y * wv1.x; acc[oi].y += hk.y * wv1.y;
                acc[oi].z += hk.y * wv1.z; acc[oi].w += hk.y * wv1.w;
                acc[oi].x += hk.z * wv2.x; acc[oi].y += hk.z * wv2.y;
                acc[oi].z += hk.z * wv2.z; acc[oi].w += hk.z * wv2.w;
                acc[oi].x += hk.w * wv3.x; acc[oi].y += hk.w * wv3.y;
                acc[oi].z += hk.w * wv3.z; acc[oi].w += hk.w * wv3.w;
            }
        }
        #pragma unroll
        for (int oi = 0; oi < 4; oi++)
            ((float4*)g_v)[(o0 + oi) * 32 + lane] = acc[oi];
    } else {
        int bx = blockIdx.x - 64;
        int half = threadIdx.x >> 7, l = threadIdx.x & 127;
        float aw0 = W1[0 * LATENT + l] + W1[(6 + 0) * LATENT + l];
        float aw1 = W1[1 * LATENT + l] + W1[(6 + 1) * LATENT + l];
        float aw2 = W1[2 * LATENT + l] + W1[(6 + 2) * LATENT + l];
        float bb = b1[l];
        #pragma unroll
        for (int qi = 0; qi < 16; qi++) {
            int q = bx * 32 + half * 16 + qi;
            float p0 = pos_query[q * 3 + 0], p1 = pos_query[q * 3 + 1], p2 = pos_query[q * 3 + 2];
            g_aq[q * LATENT + l] = bb + p0 * aw0 + p1 * aw1 + p2 * aw2;
        }
    }
}

// ---------------- kernel 2: fused logits + exp + aggregation ----------------
// grid: (N_Q/32, SEGS=9), 256 threads. Warp owns 4 queries in both phases.
// NO max-subtraction: constant shift exp(r-10) is exact algebra (cancels in combine).
__global__ __launch_bounds__(256, 2) void fused_kernel(
    const float* __restrict__ pos_query, const float* __restrict__ pos_obs,
    const int* __restrict__ query_batch, const int* __restrict__ obs_batch,
    const float* __restrict__ W1, const float* __restrict__ W2) {

    extern __shared__ __align__(16) char dyn[];
    // dyn: [0,16896) bo0  [16896,33792) bo1  [33792,+16K) v0  [+16K) v1  [WP_OFF,+18.4K) s_wp
    float* s_wp = (float*)(dyn + WP_OFF);

    __shared__ ulonglong2 s_aq[32][32];                   // 16 KB
    __shared__ ulonglong2 s_w2[32][4];                    // 2 KB
    __shared__ ulonglong2 s_wd[32];                       // 512 B
    __shared__ float4 s_po4[256];                         // 4 KB  (x,y,z,batch-bits)
    __shared__ float s_pq[32][3];
    __shared__ int s_qb[32];

    int t = threadIdx.x;
    int q0 = blockIdx.x * 32;
    int seg = blockIdx.y;
    int tile0 = seg * 7;
    int ntiles = 7 + (seg == 8 ? 1 : 0);
    int ob0 = tile0 * O_TILE;

    unsigned int dynb = (unsigned int)__cvta_generic_to_shared(dyn);
    const float4* bo4 = (const float4*)g_bo;
    const float4* v4p = (const float4*)g_v;

    // ---- stage tile 0 (bo transposed+padded, v linear) into buffer 0 ----
    {
        #pragma unroll
        for (int k = 0; k < 4; k++) {
            int i = t + k * 256;
            int oo = i >> 5, ll = i & 31;
            cpasync16(dynb + (unsigned int)(ll * 33 + oo) * 16,
                      bo4 + (size_t)(ob0 + oo) * 32 + ll);
            cpasync16(dynb + 2 * BO_BYTES + (unsigned int)i * 16,
                      v4p + (size_t)ob0 * 32 + i);
        }
        asm volatile("cp.async.commit_group;");
    }

    // ---- one-time staging ----
    const float4* aq4 = (const float4*)g_aq;
    for (int i = t; i < 1024; i += 256) {
        int q = i >> 5, lg = i & 31;
        ((float4*)s_aq)[q * 32 + lg] = aq4[(q0 + q) * 32 + lg];
    }
    for (int i = t; i < 512; i += 256) {
        int l = i >> 2, h = i & 3;
        ((float*)s_w2)[(l >> 2) * 16 + h * 4 + (l & 3)] = W2[l * 4 + h];
    }
    if (t < 128) ((float*)s_wd)[t] = W1[9 * LATENT + t];
    if (t < 32) s_qb[t] = query_batch[q0 + t];
    for (int i = t; i < 96; i += 256) {
        int r = i / 3, p = i % 3;
        s_pq[r][p] = pos_query[(q0 + r) * 3 + p];
    }
    // per-obs position + batch for this segment (256 entries)
    {
        int o = ob0 + t;
        float4 po;
        po.x = pos_obs[o * 3 + 0];
        po.y = pos_obs[o * 3 + 1];
        po.z = pos_obs[o * 3 + 2];
        po.w = __int_as_float(obs_batch[o]);
        s_po4[t] = po;
    }
    asm volatile("cp.async.wait_group 0;");
    __syncthreads();

    int warp = t >> 5, lane = t & 31;
    int qb4 = warp << 2;
    int h2 = lane >> 3;

    ull acc2[4][2];
    ull sum2[4];
    #pragma unroll
    for (int q = 0; q < 4; q++) { acc2[q][0] = 0ull; acc2[q][1] = 0ull; sum2[q] = 0ull; }

    for (int j = 0; j < ntiles; j++) {
        int og0 = ob0 + j * O_TILE;
        const ulonglong2 (*s_bo)[33] = (const ulonglong2(*)[33])(dyn + (j & 1) * BO_BYTES);
        const float4* s_v = (const float4*)(dyn + 2 * BO_BYTES + (j & 1) * V_BYTES);

        // ---- prefetch next tile (bo + v) into the other buffers ----
        if (j + 1 < ntiles) {
            unsigned int nbo = dynb + (unsigned int)(((j & 1) ^ 1) * BO_BYTES);
            unsigned int nv = dynb + 2 * BO_BYTES + (unsigned int)(((j & 1) ^ 1) * V_BYTES);
            int ng0 = og0 + O_TILE;
            #pragma unroll
            for (int k = 0; k < 4; k++) {
                int i = t + k * 256;
                int oo = i >> 5, ll = i & 31;
                cpasync16(nbo + (unsigned int)(ll * 33 + oo) * 16,
                          bo4 + (size_t)(ng0 + oo) * 32 + ll);
                cpasync16(nv + (unsigned int)i * 16,
                          v4p + (size_t)ng0 * 32 + i);
            }
            asm volatile("cp.async.commit_group;");
        }

        // ---- phase 1: logits ----
        ull d2[4];
        bool ok[4];
        {
            float4 po = s_po4[j * O_TILE + lane];
            int obv = __float_as_int(po.w);
            #pragma unroll
            for (int q = 0; q < 4; q++) {
                float dx = s_pq[qb4 + q][0] - po.x;
                float dy = s_pq[qb4 + q][1] - po.y;
                float dz = s_pq[qb4 + q][2] - po.z;
                float dv = fsqrt_approx(dx * dx + dy * dy + dz * dz);
                d2[q] = pack2(dv, dv);
                ok[q] = (s_qb[qb4 + q] == obv);
            }
        }
        ull acc1[4][4];
        #pragma unroll
        for (int q = 0; q < 4; q++)
            #pragma unroll
            for (int h = 0; h < 4; h++) acc1[q][h] = 0ull;

        #pragma unroll 4
        for (int lg = 0; lg < 32; lg++) {
            ulonglong2 bo = s_bo[lg][lane];
            ulonglong2 wd = s_wd[lg];
            ulonglong2 w0 = s_w2[lg][0], w1 = s_w2[lg][1];
            ulonglong2 w2v = s_w2[lg][2], w3 = s_w2[lg][3];
            #pragma unroll
            for (int q = 0; q < 4; q++) {
                ulonglong2 aq = s_aq[qb4 + q][lg];
                ull ta = relu2(fma2(wd.x, d2[q], add2(aq.x, bo.x)));
                ull tb = relu2(fma2(wd.y, d2[q], add2(aq.y, bo.y)));
                acc1[q][0] = fma2(ta, w0.x, acc1[q][0]);
                acc1[q][1] = fma2(ta, w1.x, acc1[q][1]);
                acc1[q][2] = fma2(ta, w2v.x, acc1[q][2]);
                acc1[q][3] = fma2(ta, w3.x, acc1[q][3]);
                acc1[q][0] = fma2(tb, w0.y, acc1[q][0]);
                acc1[q][1] = fma2(tb, w1.y, acc1[q][1]);
                acc1[q][2] = fma2(tb, w2v.y, acc1[q][2]);
                acc1[q][3] = fma2(tb, w3.y, acc1[q][3]);
            }
        }

        // ---- exp weights (no reductions, no rescale) ----
        #pragma unroll
        for (int q = 0; q < 4; q++) {
            #pragma unroll
            for (int h = 0; h < 4; h++) {
                float2 a = unpack2(acc1[q][h]);
                float r = a.x + a.y;
                float wv = ok[q] ? __expf(r - 10.0f) : 0.0f;   // constant shift: exact algebra
                s_wp[((qb4 + q) * 4 + h) * 36 + lane] = wv;
            }
        }
        __syncwarp();

        // ---- phase 2: weighted accumulation + exp-sum accumulation ----
        #pragma unroll
        for (int o4 = 0; o4 < 8; o4++) {
            ulonglong2 wq[4];
            #pragma unroll
            for (int q = 0; q < 4; q++) {
                wq[q] = *(const ulonglong2*)&s_wp[((qb4 + q) * 4 + h2) * 36 + o4 * 4];
                sum2[q] = add2(sum2[q], add2(wq[q].x, wq[q].y));
            }
            #pragma unroll
            for (int jj = 0; jj < 4; jj++) {
                int o = o4 * 4 + jj;
                float4 v4 = s_v[o * 32 + lane];
                ull v01 = pack2(v4.x, v4.y), v23 = pack2(v4.z, v4.w);
                #pragma unroll
                for (int q = 0; q < 4; q++) {
                    float2 w01 = unpack2(wq[q].x), w23 = unpack2(wq[q].y);
                    float wsc = (jj == 0) ? w01.x : (jj == 1) ? w01.y : (jj == 2) ? w23.x : w23.y;
                    ull wp = pack2(wsc, wsc);
                    acc2[q][0] = fma2(wp, v01, acc2[q][0]);
                    acc2[q][1] = fma2(wp, v23, acc2[q][1]);
                }
            }
        }

        asm volatile("cp.async.wait_group 0;");
        __syncthreads();   // single per-tile barrier
    }

    // ---- write per-segment partials ----
    if ((lane & 7) == 0) {
        #pragma unroll
        for (int q = 0; q < 4; q++) {
            float2 sp = unpack2(sum2[q]);
            int qg = q0 + qb4 + q;
            g_s2[(seg * N_Q + qg) * HEADS + h2] = sp.x + sp.y;
        }
    }
    float4* acc4 = (float4*)g_acc;
    #pragma unroll
    for (int q = 0; q < 4; q++) {
        int qg = q0 + qb4 + q;
        float2 a0 = unpack2(acc2[q][0]);
        float2 a1 = unpack2(acc2[q][1]);
        float4 r; r.x = a0.x; r.y = a0.y; r.z = a1.x; r.w = a1.y;
        acc4[(size_t)(seg * N_Q + qg) * 32 + lane] = r;
    }
}

// ---------------- kernel 3: combine segment partials (plain sum / divide) ----------------
__global__ void combine_kernel(float* __restrict__ out) {
    int idx = blockIdx.x * 256 + threadIdx.x;
    int q = idx >> 5, lq = idx & 31, h = lq >> 3;
    const float4* acc4 = (const float4*)g_acc;
    float S = 0.0f;
    float4 A; A.x = A.y = A.z = A.w = 0.0f;
    #pragma unroll
    for (int s = 0; s < SEGS; s++) {
        S += g_s2[(s * N_Q + q) * HEADS + h];
        float4 a = acc4[(size_t)(s * N_Q + q) * 32 + lq];
        A.x += a.x; A.y += a.y; A.z += a.z; A.w += a.w;
    }
    float inv = 1.0f / S;
    float4 r; r.x = A.x * inv; r.y = A.y * inv; r.z = A.z * inv; r.w = A.w * inv;
    ((float4*)out)[idx] = r;
}

// ---------------- launch ----------------
extern "C" void kernel_launch(void* const* d_in, const int* in_sizes, int n_in,
                              void* d_out, int out_size) {
    const float* h_obs      = (const float*)d_in[0];
    const float* pos_obs    = (const float*)d_in[1];
    const float* pos_query  = (const float*)d_in[2];
    const int*   obs_batch  = (const int*)d_in[3];
    const int*   query_batch= (const int*)d_in[4];
    const float* W1         = (const float*)d_in[5];
    const float* b1         = (const float*)d_in[6];
    const float* W2         = (const float*)d_in[7];
    const float* ln_gamma   = (const float*)d_in[9];
    const float* ln_beta    = (const float*)d_in[10];
    const float* Wv         = (const float*)d_in[11];
    const float* bv         = (const float*)d_in[12];
    float* out = (float*)d_out;

    cudaFuncSetAttribute(fused_kernel, cudaFuncAttributeMaxDynamicSharedMemorySize, DYN_BYTES);

    pre_kernel<<<96, 256>>>(h_obs, pos_obs, pos_query, W1, b1, ln_gamma, ln_beta, Wv, bv);
    fused_kernel<<<dim3(N_Q / 32, SEGS), 256, DYN_BYTES>>>(
        pos_query, pos_obs, query_batch, obs_batch, W1, W2);
    combine_kernel<<<(N_Q * 32) / 256, 256>>>(out);
}

// round 16
// speedup vs baseline: 1.0869x; 1.0869x over previous
#include <cuda_runtime.h>
#include <cstdint>

#define N_Q 1024
#define N_O 2048
#define LATENT 128
#define HEADS 4
#define SEGS 9
#define O_TILE 32
// tiles: 64 total; segs 0..7 get 7 tiles, seg 8 gets 8

#define BO_BYTES 16896                                  // 32 rows x 33 ulonglong2 (padded, transposed)
#define V_BYTES 16384
#define WP_OFF (2 * BO_BYTES + 2 * V_BYTES)             // 66560
#define DYN_BYTES (WP_OFF + 8 * 16 * 36 * 4)            // 66560 + 18432 = 84992

typedef unsigned long long ull;

// ---------------- scratch (static device globals; no allocation) ----------------
__device__ float g_v[N_O * LATENT];
__device__ float g_bo[N_O * LATENT];
__device__ float g_aq[N_Q * LATENT];
__device__ float g_s2[SEGS * N_Q * HEADS];              // per-segment exp-sums
__device__ float g_acc[SEGS * N_Q * LATENT];            // per-segment weighted partials

// ---------------- packed f32x2 helpers ----------------
__device__ __forceinline__ ull fma2(ull a, ull b, ull c) {
    ull d; asm("fma.rn.f32x2 %0, %1, %2, %3;" : "=l"(d) : "l"(a), "l"(b), "l"(c)); return d;
}
__device__ __forceinline__ ull add2(ull a, ull b) {
    ull d; asm("add.rn.f32x2 %0, %1, %2;" : "=l"(d) : "l"(a), "l"(b)); return d;
}
__device__ __forceinline__ ull relu2(ull a) {
    ull d;
    asm("{\n\t"
        ".reg .f32 lo, hi;\n\t"
        "mov.b64 {lo, hi}, %1;\n\t"
        "max.f32 lo, lo, 0f00000000;\n\t"
        "max.f32 hi, hi, 0f00000000;\n\t"
        "mov.b64 %0, {lo, hi};\n\t"
        "}" : "=l"(d) : "l"(a));
    return d;
}
__device__ __forceinline__ ull pack2(float x, float y) {
    ull d; asm("mov.b64 %0, {%1, %2};" : "=l"(d) : "f"(x), "f"(y)); return d;
}
__device__ __forceinline__ float2 unpack2(ull a) {
    float2 f; asm("mov.b64 {%0, %1}, %2;" : "=f"(f.x), "=f"(f.y) : "l"(a)); return f;
}
__device__ __forceinline__ void cpasync16(unsigned int saddr, const void* gaddr) {
    asm volatile("cp.async.cg.shared.global [%0], [%1], 16;" :: "r"(saddr), "l"(gaddr));
}
__device__ __forceinline__ float fsqrt_approx(float x) {
    float r; asm("sqrt.approx.f32 %0, %1;" : "=f"(r) : "f"(x)); return r;
}

// ---------------- kernel 1: precompute (R13 warp-per-obs, 128-thread blocks) ----------------
// Blocks 0..511: obs (block = 4 obs, warp = 1 obs, lane = 4 latents).
// Blocks 512..575: queries (block = 16 q).
__global__ __launch_bounds__(128) void pre_kernel(
    const float* __restrict__ h_obs,
    const float* __restrict__ pos_obs,
    const float* __restrict__ pos_query,
    const float* __restrict__ W1,
    const float* __restrict__ b1,
    const float* __restrict__ ln_gamma,
    const float* __restrict__ ln_beta,
    const float* __restrict__ Wv,
    const float* __restrict__ bv) {

    if (blockIdx.x < 512) {
        __shared__ float s_hn[4][LATENT];
        int warp = threadIdx.x >> 5, lane = threadIdx.x & 31;
        int o = blockIdx.x * 4 + warp;

        const float4* h4p = (const float4*)h_obs;
        const float4* W14 = (const float4*)W1;
        float4 h = h4p[o * 32 + lane];
        float s1 = h.x + h.y + h.z + h.w;
        float s2 = h.x * h.x + h.y * h.y + h.z * h.z + h.w * h.w;
        #pragma unroll
        for (int off = 16; off; off >>= 1) {
            s1 += __shfl_xor_sync(0xffffffffu, s1, off);
            s2 += __shfl_xor_sync(0xffffffffu, s2, off);
        }
        float mu = s1 * (1.0f / LATENT);
        float var = s2 * (1.0f / LATENT) - mu * mu;
        float rs = rsqrtf(var + 1e-5f);
        float4 gam = ((const float4*)ln_gamma)[lane];
        float4 bet = ((const float4*)ln_beta)[lane];
        float4 hn;
        hn.x = (h.x - mu) * rs * gam.x + bet.x;
        hn.y = (h.y - mu) * rs * gam.y + bet.y;
        hn.z = (h.z - mu) * rs * gam.z + bet.z;
        hn.w = (h.w - mu) * rs * gam.w + bet.w;
        ((float4*)s_hn[warp])[lane] = hn;

        // bo for this obs
        float4 bw0, bw1, bw2;
        {
            float4 a3 = W14[3 * 32 + lane], a4 = W14[4 * 32 + lane], a5 = W14[5 * 32 + lane];
            float4 a6 = W14[6 * 32 + lane], a7 = W14[7 * 32 + lane], a8 = W14[8 * 32 + lane];
            bw0.x = a3.x - a6.x; bw0.y = a3.y - a6.y; bw0.z = a3.z - a6.z; bw0.w = a3.w - a6.w;
            bw1.x = a4.x - a7.x; bw1.y = a4.y - a7.y; bw1.z = a4.z - a7.z; bw1.w = a4.w - a7.w;
            bw2.x = a5.x - a8.x; bw2.y = a5.y - a8.y; bw2.z = a5.z - a8.z; bw2.w = a5.w - a8.w;
        }
        float p0 = pos_obs[o * 3 + 0], p1 = pos_obs[o * 3 + 1], p2 = pos_obs[o * 3 + 2];
        float4 bo;
        bo.x = p0 * bw0.x + p1 * bw1.x + p2 * bw2.x;
        bo.y = p0 * bw0.y + p1 * bw1.y + p2 * bw2.y;
        bo.z = p0 * bw0.z + p1 * bw1.z + p2 * bw2.z;
        bo.w = p0 * bw0.w + p1 * bw1.w + p2 * bw2.w;
        ((float4*)g_bo)[o * 32 + lane] = bo;
        __syncwarp();

        // v = hn @ Wv + bv (warp-local; k-loop unrolled for MLP)
        float4 acc = ((const float4*)bv)[lane];
        const float4* wv4 = (const float4*)Wv;
        const float* hnr = s_hn[warp];
        #pragma unroll 8
        for (int k = 0; k < LATENT; k++) {
            float4 wv = wv4[k * 32 + lane];
            float hk = hnr[k];
            acc.x += hk * wv.x;
            acc.y += hk * wv.y;
            acc.z += hk * wv.z;
            acc.w += hk * wv.w;
        }
        ((float4*)g_v)[o * 32 + lane] = acc;
    } else {
        int bx = blockIdx.x - 512;
        int l = threadIdx.x;
        float aw0 = W1[0 * LATENT + l] + W1[(6 + 0) * LATENT + l];
        float aw1 = W1[1 * LATENT + l] + W1[(6 + 1) * LATENT + l];
        float aw2 = W1[2 * LATENT + l] + W1[(6 + 2) * LATENT + l];
        float bb = b1[l];
        #pragma unroll
        for (int qi = 0; qi < 16; qi++) {
            int q = bx * 16 + qi;
            float p0 = pos_query[q * 3 + 0], p1 = pos_query[q * 3 + 1], p2 = pos_query[q * 3 + 2];
            g_aq[q * LATENT + l] = bb + p0 * aw0 + p1 * aw1 + p2 * aw2;
        }
    }
}

// ---------------- kernel 2: fused logits + exp + aggregation ----------------
// grid: (N_Q/32, SEGS=9), 256 threads. Warp owns 4 queries in both phases.
// NO max-subtraction: constant shift exp(r-10) is exact algebra (cancels in combine).
__global__ __launch_bounds__(256, 2) void fused_kernel(
    const float* __restrict__ pos_query, const float* __restrict__ pos_obs,
    const int* __restrict__ query_batch, const int* __restrict__ obs_batch,
    const float* __restrict__ W1, const float* __restrict__ W2) {

    extern __shared__ __align__(16) char dyn[];
    // dyn: [0,16896) bo0  [16896,33792) bo1  [33792,+16K) v0  [+16K) v1  [WP_OFF,+18.4K) s_wp
    float* s_wp = (float*)(dyn + WP_OFF);

    __shared__ ulonglong2 s_aq[32][32];                   // 16 KB
    __shared__ ulonglong2 s_w2[32][4];                    // 2 KB
    __shared__ ulonglong2 s_wd[32];                       // 512 B
    __shared__ float4 s_po4[256];                         // 4 KB  (x,y,z,batch-bits)
    __shared__ float s_pq[32][3];
    __shared__ int s_qb[32];

    int t = threadIdx.x;
    int q0 = blockIdx.x * 32;
    int seg = blockIdx.y;
    int tile0 = seg * 7;
    int ntiles = 7 + (seg == 8 ? 1 : 0);
    int ob0 = tile0 * O_TILE;

    unsigned int dynb = (unsigned int)__cvta_generic_to_shared(dyn);
    const float4* bo4 = (const float4*)g_bo;
    const float4* v4p = (const float4*)g_v;

    // ---- stage tile 0 (bo transposed+padded, v linear) into buffer 0 ----
    {
        #pragma unroll
        for (int k = 0; k < 4; k++) {
            int i = t + k * 256;
            int oo = i >> 5, ll = i & 31;
            cpasync16(dynb + (unsigned int)(ll * 33 + oo) * 16,
                      bo4 + (size_t)(ob0 + oo) * 32 + ll);
            cpasync16(dynb + 2 * BO_BYTES + (unsigned int)i * 16,
                      v4p + (size_t)ob0 * 32 + i);
        }
        asm volatile("cp.async.commit_group;");
    }

    // ---- one-time staging ----
    const float4* aq4 = (const float4*)g_aq;
    for (int i = t; i < 1024; i += 256) {
        int q = i >> 5, lg = i & 31;
        ((float4*)s_aq)[q * 32 + lg] = aq4[(q0 + q) * 32 + lg];
    }
    for (int i = t; i < 512; i += 256) {
        int l = i >> 2, h = i & 3;
        ((float*)s_w2)[(l >> 2) * 16 + h * 4 + (l & 3)] = W2[l * 4 + h];
    }
    if (t < 128) ((float*)s_wd)[t] = W1[9 * LATENT + t];
    if (t < 32) s_qb[t] = query_batch[q0 + t];
    for (int i = t; i < 96; i += 256) {
        int r = i / 3, p = i % 3;
        s_pq[r][p] = pos_query[(q0 + r) * 3 + p];
    }
    // per-obs position + batch for this segment (256 entries)
    {
        int o = ob0 + t;
        float4 po;
        po.x = pos_obs[o * 3 + 0];
        po.y = pos_obs[o * 3 + 1];
        po.z = pos_obs[o * 3 + 2];
        po.w = __int_as_float(obs_batch[o]);
        s_po4[t] = po;
    }
    asm volatile("cp.async.wait_group 0;");
    __syncthreads();

    int warp = t >> 5, lane = t & 31;
    int qb4 = warp << 2;
    int h2 = lane >> 3;

    ull acc2[4][2];
    ull sum2[4];
    #pragma unroll
    for (int q = 0; q < 4; q++) { acc2[q][0] = 0ull; acc2[q][1] = 0ull; sum2[q] = 0ull; }

    for (int j = 0; j < ntiles; j++) {
        int og0 = ob0 + j * O_TILE;
        const ulonglong2 (*s_bo)[33] = (const ulonglong2(*)[33])(dyn + (j & 1) * BO_BYTES);
        const float4* s_v = (const float4*)(dyn + 2 * BO_BYTES + (j & 1) * V_BYTES);

        // ---- prefetch next tile (bo + v) into the other buffers ----
        if (j + 1 < ntiles) {
            unsigned int nbo = dynb + (unsigned int)(((j & 1) ^ 1) * BO_BYTES);
            unsigned int nv = dynb + 2 * BO_BYTES + (unsigned int)(((j & 1) ^ 1) * V_BYTES);
            int ng0 = og0 + O_TILE;
            #pragma unroll
            for (int k = 0; k < 4; k++) {
                int i = t + k * 256;
                int oo = i >> 5, ll = i & 31;
                cpasync16(nbo + (unsigned int)(ll * 33 + oo) * 16,
                          bo4 + (size_t)(ng0 + oo) * 32 + ll);
                cpasync16(nv + (unsigned int)i * 16,
                          v4p + (size_t)ng0 * 32 + i);
            }
            asm volatile("cp.async.commit_group;");
        }

        // ---- phase 1: logits ----
        ull d2[4];
        bool ok[4];
        {
            float4 po = s_po4[j * O_TILE + lane];
            int obv = __float_as_int(po.w);
            #pragma unroll
            for (int q = 0; q < 4; q++) {
                float dx = s_pq[qb4 + q][0] - po.x;
                float dy = s_pq[qb4 + q][1] - po.y;
                float dz = s_pq[qb4 + q][2] - po.z;
                float dv = fsqrt_approx(dx * dx + dy * dy + dz * dz);
                d2[q] = pack2(dv, dv);
                ok[q] = (s_qb[qb4 + q] == obv);
            }
        }
        ull acc1[4][4];
        #pragma unroll
        for (int q = 0; q < 4; q++)
            #pragma unroll
            for (int h = 0; h < 4; h++) acc1[q][h] = 0ull;

        #pragma unroll 4
        for (int lg = 0; lg < 32; lg++) {
            ulonglong2 bo = s_bo[lg][lane];
            ulonglong2 wd = s_wd[lg];
            ulonglong2 w0 = s_w2[lg][0], w1 = s_w2[lg][1];
            ulonglong2 w2v = s_w2[lg][2], w3 = s_w2[lg][3];
            #pragma unroll
            for (int q = 0; q < 4; q++) {
                ulonglong2 aq = s_aq[qb4 + q][lg];
                ull ta = relu2(fma2(wd.x, d2[q], add2(aq.x, bo.x)));
                ull tb = relu2(fma2(wd.y, d2[q], add2(aq.y, bo.y)));
                acc1[q][0] = fma2(ta, w0.x, acc1[q][0]);
                acc1[q][1] = fma2(ta, w1.x, acc1[q][1]);
                acc1[q][2] = fma2(ta, w2v.x, acc1[q][2]);
                acc1[q][3] = fma2(ta, w3.x, acc1[q][3]);
                acc1[q][0] = fma2(tb, w0.y, acc1[q][0]);
                acc1[q][1] = fma2(tb, w1.y, acc1[q][1]);
                acc1[q][2] = fma2(tb, w2v.y, acc1[q][2]);
                acc1[q][3] = fma2(tb, w3.y, acc1[q][3]);
            }
        }

        // ---- exp weights (no reductions, no rescale) ----
        #pragma unroll
        for (int q = 0; q < 4; q++) {
            #pragma unroll
            for (int h = 0; h < 4; h++) {
                float2 a = unpack2(acc1[q][h]);
                float r = a.x + a.y;
                float wv = ok[q] ? __expf(r - 10.0f) : 0.0f;   // constant shift: exact algebra
                s_wp[((qb4 + q) * 4 + h) * 36 + lane] = wv;
            }
        }
        __syncwarp();

        // ---- phase 2: weighted accumulation + exp-sum accumulation ----
        #pragma unroll
        for (int o4 = 0; o4 < 8; o4++) {
            ulonglong2 wq[4];
            #pragma unroll
            for (int q = 0; q < 4; q++) {
                wq[q] = *(const ulonglong2*)&s_wp[((qb4 + q) * 4 + h2) * 36 + o4 * 4];
                sum2[q] = add2(sum2[q], add2(wq[q].x, wq[q].y));
            }
            #pragma unroll
            for (int jj = 0; jj < 4; jj++) {
                int o = o4 * 4 + jj;
                float4 v4 = s_v[o * 32 + lane];
                ull v01 = pack2(v4.x, v4.y), v23 = pack2(v4.z, v4.w);
                #pragma unroll
                for (int q = 0; q < 4; q++) {
                    float2 w01 = unpack2(wq[q].x), w23 = unpack2(wq[q].y);
                    float wsc = (jj == 0) ? w01.x : (jj == 1) ? w01.y : (jj == 2) ? w23.x : w23.y;
                    ull wp = pack2(wsc, wsc);
                    acc2[q][0] = fma2(wp, v01, acc2[q][0]);
                    acc2[q][1] = fma2(wp, v23, acc2[q][1]);
                }
            }
        }

        asm volatile("cp.async.wait_group 0;");
        __syncthreads();   // single per-tile barrier
    }

    // ---- write per-segment partials ----
    if ((lane & 7) == 0) {
        #pragma unroll
        for (int q = 0; q < 4; q++) {
            float2 sp = unpack2(sum2[q]);
            int qg = q0 + qb4 + q;
            g_s2[(seg * N_Q + qg) * HEADS + h2] = sp.x + sp.y;
        }
    }
    float4* acc4 = (float4*)g_acc;
    #pragma unroll
    for (int q = 0; q < 4; q++) {
        int qg = q0 + qb4 + q;
        float2 a0 = unpack2(acc2[q][0]);
        float2 a1 = unpack2(acc2[q][1]);
        float4 r; r.x = a0.x; r.y = a0.y; r.z = a1.x; r.w = a1.y;
        acc4[(size_t)(seg * N_Q + qg) * 32 + lane] = r;
    }
}

// ---------------- kernel 3: combine segment partials (plain sum / divide) ----------------
__global__ void combine_kernel(float* __restrict__ out) {
    int idx = blockIdx.x * 256 + threadIdx.x;
    int q = idx >> 5, lq = idx & 31, h = lq >> 3;
    const float4* acc4 = (const float4*)g_acc;
    float S = 0.0f;
    float4 A; A.x = A.y = A.z = A.w = 0.0f;
    #pragma unroll
    for (int s = 0; s < SEGS; s++) {
        S += g_s2[(s * N_Q + q) * HEADS + h];
        float4 a = acc4[(size_t)(s * N_Q + q) * 32 + lq];
        A.x += a.x; A.y += a.y; A.z += a.z; A.w += a.w;
    }
    float inv = 1.0f / S;
    float4 r; r.x = A.x * inv; r.y = A.y * inv; r.z = A.z * inv; r.w = A.w * inv;
    ((float4*)out)[idx] = r;
}

// ---------------- launch ----------------
extern "C" void kernel_launch(void* const* d_in, const int* in_sizes, int n_in,
                              void* d_out, int out_size) {
    const float* h_obs      = (const float*)d_in[0];
    const float* pos_obs    = (const float*)d_in[1];
    const float* pos_query  = (const float*)d_in[2];
    const int*   obs_batch  = (const int*)d_in[3];
    const int*   query_batch= (const int*)d_in[4];
    const float* W1         = (const float*)d_in[5];
    const float* b1         = (const float*)d_in[6];
    const float* W2         = (const float*)d_in[7];
    const float* ln_gamma   = (const float*)d_in[9];
    const float* ln_beta    = (const float*)d_in[10];
    const float* Wv         = (const float*)d_in[11];
    const float* bv         = (const float*)d_in[12];
    float* out = (float*)d_out;

    cudaFuncSetAttribute(fused_kernel, cudaFuncAttributeMaxDynamicSharedMemorySize, DYN_BYTES);

    pre_kernel<<<576, 128>>>(h_obs, pos_obs, pos_query, W1, b1, ln_gamma, ln_beta, Wv, bv);
    fused_kernel<<<dim3(N_Q / 32, SEGS), 256, DYN_BYTES>>>(
        pos_query, pos_obs, query_batch, obs_batch, W1, W2);
    combine_kernel<<<(N_Q * 32) / 256, 256>>>(out);
}

// round 17
// speedup vs baseline: 1.0900x; 1.0029x over previous
#include <cuda_runtime.h>
#include <cstdint>

#define N_Q 1024
#define N_O 2048
#define LATENT 128
#define HEADS 4
#define SEGS 9
#define O_TILE 32
// tiles: 64 total; segs 0..7 get 7 tiles, seg 8 gets 8

#define BO_BYTES 16896                                  // 32 rows x 33 ulonglong2 (padded, transposed)
#define V_BYTES 16384
#define WP_OFF (2 * BO_BYTES + 2 * V_BYTES)             // 66560
#define DYN_BYTES (WP_OFF + 8 * 16 * 36 * 4)            // 66560 + 18432 = 84992

typedef unsigned long long ull;

// ---------------- scratch (static device globals; no allocation) ----------------
__device__ float g_v[N_O * LATENT];
__device__ float g_bo[N_O * LATENT];
__device__ float g_aq[N_Q * LATENT];
__device__ float g_s2[SEGS * N_Q * HEADS];              // per-segment exp-sums
__device__ float g_acc[SEGS * N_Q * LATENT];            // per-segment weighted partials

// ---------------- packed f32x2 helpers ----------------
__device__ __forceinline__ ull fma2(ull a, ull b, ull c) {
    ull d; asm("fma.rn.f32x2 %0, %1, %2, %3;" : "=l"(d) : "l"(a), "l"(b), "l"(c)); return d;
}
__device__ __forceinline__ ull add2(ull a, ull b) {
    ull d; asm("add.rn.f32x2 %0, %1, %2;" : "=l"(d) : "l"(a), "l"(b)); return d;
}
__device__ __forceinline__ ull relu2(ull a) {
    ull d;
    asm("{\n\t"
        ".reg .f32 lo, hi;\n\t"
        "mov.b64 {lo, hi}, %1;\n\t"
        "max.f32 lo, lo, 0f00000000;\n\t"
        "max.f32 hi, hi, 0f00000000;\n\t"
        "mov.b64 %0, {lo, hi};\n\t"
        "}" : "=l"(d) : "l"(a));
    return d;
}
__device__ __forceinline__ ull pack2(float x, float y) {
    ull d; asm("mov.b64 %0, {%1, %2};" : "=l"(d) : "f"(x), "f"(y)); return d;
}
__device__ __forceinline__ float2 unpack2(ull a) {
    float2 f; asm("mov.b64 {%0, %1}, %2;" : "=f"(f.x), "=f"(f.y) : "l"(a)); return f;
}
__device__ __forceinline__ void cpasync16(unsigned int saddr, const void* gaddr) {
    asm volatile("cp.async.cg.shared.global [%0], [%1], 16;" :: "r"(saddr), "l"(gaddr));
}
__device__ __forceinline__ float fsqrt_approx(float x) {
    float r; asm("sqrt.approx.f32 %0, %1;" : "=f"(r) : "f"(x)); return r;
}

// ---------------- kernel 1: precompute (warp-per-obs; batched-MLP v-GEMV) ----------------
// Blocks 0..511: obs (block = 4 obs, warp = 1 obs, lane = 4 latents).
// Blocks 512..575: queries (block = 16 q).
__global__ __launch_bounds__(128) void pre_kernel(
    const float* __restrict__ h_obs,
    const float* __restrict__ pos_obs,
    const float* __restrict__ pos_query,
    const float* __restrict__ W1,
    const float* __restrict__ b1,
    const float* __restrict__ ln_gamma,
    const float* __restrict__ ln_beta,
    const float* __restrict__ Wv,
    const float* __restrict__ bv) {

    if (blockIdx.x < 512) {
        __shared__ float s_hn[4][LATENT];
        int warp = threadIdx.x >> 5, lane = threadIdx.x & 31;
        int o = blockIdx.x * 4 + warp;

        const float4* h4p = (const float4*)h_obs;
        const float4* W14 = (const float4*)W1;
        float4 h = h4p[o * 32 + lane];
        float s1 = h.x + h.y + h.z + h.w;
        float s2 = h.x * h.x + h.y * h.y + h.z * h.z + h.w * h.w;
        #pragma unroll
        for (int off = 16; off; off >>= 1) {
            s1 += __shfl_xor_sync(0xffffffffu, s1, off);
            s2 += __shfl_xor_sync(0xffffffffu, s2, off);
        }
        float mu = s1 * (1.0f / LATENT);
        float var = s2 * (1.0f / LATENT) - mu * mu;
        float rs = rsqrtf(var + 1e-5f);
        float4 gam = ((const float4*)ln_gamma)[lane];
        float4 bet = ((const float4*)ln_beta)[lane];
        float4 hn;
        hn.x = (h.x - mu) * rs * gam.x + bet.x;
        hn.y = (h.y - mu) * rs * gam.y + bet.y;
        hn.z = (h.z - mu) * rs * gam.z + bet.z;
        hn.w = (h.w - mu) * rs * gam.w + bet.w;
        ((float4*)s_hn[warp])[lane] = hn;

        // bo for this obs
        float4 bw0, bw1, bw2;
        {
            float4 a3 = W14[3 * 32 + lane], a4 = W14[4 * 32 + lane], a5 = W14[5 * 32 + lane];
            float4 a6 = W14[6 * 32 + lane], a7 = W14[7 * 32 + lane], a8 = W14[8 * 32 + lane];
            bw0.x = a3.x - a6.x; bw0.y = a3.y - a6.y; bw0.z = a3.z - a6.z; bw0.w = a3.w - a6.w;
            bw1.x = a4.x - a7.x; bw1.y = a4.y - a7.y; bw1.z = a4.z - a7.z; bw1.w = a4.w - a7.w;
            bw2.x = a5.x - a8.x; bw2.y = a5.y - a8.y; bw2.z = a5.z - a8.z; bw2.w = a5.w - a8.w;
        }
        float p0 = pos_obs[o * 3 + 0], p1 = pos_obs[o * 3 + 1], p2 = pos_obs[o * 3 + 2];
        float4 bo;
        bo.x = p0 * bw0.x + p1 * bw1.x + p2 * bw2.x;
        bo.y = p0 * bw0.y + p1 * bw1.y + p2 * bw2.y;
        bo.z = p0 * bw0.z + p1 * bw1.z + p2 * bw2.z;
        bo.w = p0 * bw0.w + p1 * bw1.w + p2 * bw2.w;
        ((float4*)g_bo)[o * 32 + lane] = bo;
        __syncwarp();

        // v = hn @ Wv + bv — fully unrolled, 16 LDG.128 batched per group (MLP ~16)
        float4 acc = ((const float4*)bv)[lane];
        const float4* wv4 = (const float4*)Wv;
        const float4* hn4 = (const float4*)s_hn[warp];
        #pragma unroll
        for (int g = 0; g < 8; g++) {
            float4 w[16];
            #pragma unroll
            for (int i = 0; i < 16; i++)
                w[i] = wv4[(g * 16 + i) * 32 + lane];
            float4 hk[4];
            #pragma unroll
            for (int i = 0; i < 4; i++)
                hk[i] = hn4[g * 4 + i];
            #pragma unroll
            for (int i = 0; i < 4; i++) {
                acc.x += hk[i].x * w[i*4+0].x; acc.y += hk[i].x * w[i*4+0].y;
                acc.z += hk[i].x * w[i*4+0].z; acc.w += hk[i].x * w[i*4+0].w;
                acc.x += hk[i].y * w[i*4+1].x; acc.y += hk[i].y * w[i*4+1].y;
                acc.z += hk[i].y * w[i*4+1].z; acc.w += hk[i].y * w[i*4+1].w;
                acc.x += hk[i].z * w[i*4+2].x; acc.y += hk[i].z * w[i*4+2].y;
                acc.z += hk[i].z * w[i*4+2].z; acc.w += hk[i].z * w[i*4+2].w;
                acc.x += hk[i].w * w[i*4+3].x; acc.y += hk[i].w * w[i*4+3].y;
                acc.z += hk[i].w * w[i*4+3].z; acc.w += hk[i].w * w[i*4+3].w;
            }
        }
        ((float4*)g_v)[o * 32 + lane] = acc;
    } else {
        int bx = blockIdx.x - 512;
        int l = threadIdx.x;
        float aw0 = W1[0 * LATENT + l] + W1[(6 + 0) * LATENT + l];
        float aw1 = W1[1 * LATENT + l] + W1[(6 + 1) * LATENT + l];
        float aw2 = W1[2 * LATENT + l] + W1[(6 + 2) * LATENT + l];
        float bb = b1[l];
        #pragma unroll
        for (int qi = 0; qi < 16; qi++) {
            int q = bx * 16 + qi;
            float p0 = pos_query[q * 3 + 0], p1 = pos_query[q * 3 + 1], p2 = pos_query[q * 3 + 2];
            g_aq[q * LATENT + l] = bb + p0 * aw0 + p1 * aw1 + p2 * aw2;
        }
    }
}

// ---------------- kernel 2: fused logits + exp + aggregation ----------------
// grid: (N_Q/32, SEGS=9), 256 threads. Warp owns 4 queries in both phases.
// NO max-subtraction: constant shift exp(r-10) is exact algebra (cancels in combine).
__global__ __launch_bounds__(256, 2) void fused_kernel(
    const float* __restrict__ pos_query, const float* __restrict__ pos_obs,
    const int* __restrict__ query_batch, const int* __restrict__ obs_batch,
    const float* __restrict__ W1, const float* __restrict__ W2) {

    extern __shared__ __align__(16) char dyn[];
    // dyn: [0,16896) bo0  [16896,33792) bo1  [33792,+16K) v0  [+16K) v1  [WP_OFF,+18.4K) s_wp
    float* s_wp = (float*)(dyn + WP_OFF);

    __shared__ ulonglong2 s_aq[32][32];                   // 16 KB
    __shared__ ulonglong2 s_w2[32][4];                    // 2 KB
    __shared__ ulonglong2 s_wd[32];                       // 512 B
    __shared__ float4 s_po4[256];                         // 4 KB  (x,y,z,batch-bits)
    __shared__ float s_pq[32][3];
    __shared__ int s_qb[32];

    int t = threadIdx.x;
    int q0 = blockIdx.x * 32;
    int seg = blockIdx.y;
    int tile0 = seg * 7;
    int ntiles = 7 + (seg == 8 ? 1 : 0);
    int ob0 = tile0 * O_TILE;

    unsigned int dynb = (unsigned int)__cvta_generic_to_shared(dyn);
    const float4* bo4 = (const float4*)g_bo;
    const float4* v4p = (const float4*)g_v;

    // ---- stage tile 0 (bo transposed+padded, v linear) into buffer 0 ----
    {
        #pragma unroll
        for (int k = 0; k < 4; k++) {
            int i = t + k * 256;
            int oo = i >> 5, ll = i & 31;
            cpasync16(dynb + (unsigned int)(ll * 33 + oo) * 16,
                      bo4 + (size_t)(ob0 + oo) * 32 + ll);
            cpasync16(dynb + 2 * BO_BYTES + (unsigned int)i * 16,
                      v4p + (size_t)ob0 * 32 + i);
        }
        asm volatile("cp.async.commit_group;");
    }

    // ---- one-time staging ----
    const float4* aq4 = (const float4*)g_aq;
    for (int i = t; i < 1024; i += 256) {
        int q = i >> 5, lg = i & 31;
        ((float4*)s_aq)[q * 32 + lg] = aq4[(q0 + q) * 32 + lg];
    }
    for (int i = t; i < 512; i += 256) {
        int l = i >> 2, h = i & 3;
        ((float*)s_w2)[(l >> 2) * 16 + h * 4 + (l & 3)] = W2[l * 4 + h];
    }
    if (t < 128) ((float*)s_wd)[t] = W1[9 * LATENT + t];
    if (t < 32) s_qb[t] = query_batch[q0 + t];
    for (int i = t; i < 96; i += 256) {
        int r = i / 3, p = i % 3;
        s_pq[r][p] = pos_query[(q0 + r) * 3 + p];
    }
    // per-obs position + batch for this segment (256 entries)
    {
        int o = ob0 + t;
        float4 po;
        po.x = pos_obs[o * 3 + 0];
        po.y = pos_obs[o * 3 + 1];
        po.z = pos_obs[o * 3 + 2];
        po.w = __int_as_float(obs_batch[o]);
        s_po4[t] = po;
    }
    asm volatile("cp.async.wait_group 0;");
    __syncthreads();

    int warp = t >> 5, lane = t & 31;
    int qb4 = warp << 2;
    int h2 = lane >> 3;

    ull acc2[4][2];
    ull sum2[4];
    #pragma unroll
    for (int q = 0; q < 4; q++) { acc2[q][0] = 0ull; acc2[q][1] = 0ull; sum2[q] = 0ull; }

    for (int j = 0; j < ntiles; j++) {
        int og0 = ob0 + j * O_TILE;
        const ulonglong2 (*s_bo)[33] = (const ulonglong2(*)[33])(dyn + (j & 1) * BO_BYTES);
        const float4* s_v = (const float4*)(dyn + 2 * BO_BYTES + (j & 1) * V_BYTES);

        // ---- prefetch next tile (bo + v) into the other buffers ----
        if (j + 1 < ntiles) {
            unsigned int nbo = dynb + (unsigned int)(((j & 1) ^ 1) * BO_BYTES);
            unsigned int nv = dynb + 2 * BO_BYTES + (unsigned int)(((j & 1) ^ 1) * V_BYTES);
            int ng0 = og0 + O_TILE;
            #pragma unroll
            for (int k = 0; k < 4; k++) {
                int i = t + k * 256;
                int oo = i >> 5, ll = i & 31;
                cpasync16(nbo + (unsigned int)(ll * 33 + oo) * 16,
                          bo4 + (size_t)(ng0 + oo) * 32 + ll);
                cpasync16(nv + (unsigned int)i * 16,
                          v4p + (size_t)ng0 * 32 + i);
            }
            asm volatile("cp.async.commit_group;");
        }

        // ---- phase 1: logits ----
        ull d2[4];
        bool ok[4];
        {
            float4 po = s_po4[j * O_TILE + lane];
            int obv = __float_as_int(po.w);
            #pragma unroll
            for (int q = 0; q < 4; q++) {
                float dx = s_pq[qb4 + q][0] - po.x;
                float dy = s_pq[qb4 + q][1] - po.y;
                float dz = s_pq[qb4 + q][2] - po.z;
                float dv = fsqrt_approx(dx * dx + dy * dy + dz * dz);
                d2[q] = pack2(dv, dv);
                ok[q] = (s_qb[qb4 + q] == obv);
            }
        }
        ull acc1[4][4];
        #pragma unroll
        for (int q = 0; q < 4; q++)
            #pragma unroll
            for (int h = 0; h < 4; h++) acc1[q][h] = 0ull;

        #pragma unroll 4
        for (int lg = 0; lg < 32; lg++) {
            ulonglong2 bo = s_bo[lg][lane];
            ulonglong2 wd = s_wd[lg];
            ulonglong2 w0 = s_w2[lg][0], w1 = s_w2[lg][1];
            ulonglong2 w2v = s_w2[lg][2], w3 = s_w2[lg][3];
            #pragma unroll
            for (int q = 0; q < 4; q++) {
                ulonglong2 aq = s_aq[qb4 + q][lg];
                ull ta = relu2(fma2(wd.x, d2[q], add2(aq.x, bo.x)));
                ull tb = relu2(fma2(wd.y, d2[q], add2(aq.y, bo.y)));
                acc1[q][0] = fma2(ta, w0.x, acc1[q][0]);
                acc1[q][1] = fma2(ta, w1.x, acc1[q][1]);
                acc1[q][2] = fma2(ta, w2v.x, acc1[q][2]);
                acc1[q][3] = fma2(ta, w3.x, acc1[q][3]);
                acc1[q][0] = fma2(tb, w0.y, acc1[q][0]);
                acc1[q][1] = fma2(tb, w1.y, acc1[q][1]);
                acc1[q][2] = fma2(tb, w2v.y, acc1[q][2]);
                acc1[q][3] = fma2(tb, w3.y, acc1[q][3]);
            }
        }

        // ---- exp weights (no reductions, no rescale) ----
        #pragma unroll
        for (int q = 0; q < 4; q++) {
            #pragma unroll
            for (int h = 0; h < 4; h++) {
                float2 a = unpack2(acc1[q][h]);
                float r = a.x + a.y;
                float wv = ok[q] ? __expf(r - 10.0f) : 0.0f;   // constant shift: exact algebra
                s_wp[((qb4 + q) * 4 + h) * 36 + lane] = wv;
            }
        }
        __syncwarp();

        // ---- phase 2: weighted accumulation + exp-sum accumulation ----
        #pragma unroll
        for (int o4 = 0; o4 < 8; o4++) {
            ulonglong2 wq[4];
            #pragma unroll
            for (int q = 0; q < 4; q++) {
                wq[q] = *(const ulonglong2*)&s_wp[((qb4 + q) * 4 + h2) * 36 + o4 * 4];
                sum2[q] = add2(sum2[q], add2(wq[q].x, wq[q].y));
            }
            #pragma unroll
            for (int jj = 0; jj < 4; jj++) {
                int o = o4 * 4 + jj;
                float4 v4 = s_v[o * 32 + lane];
                ull v01 = pack2(v4.x, v4.y), v23 = pack2(v4.z, v4.w);
                #pragma unroll
                for (int q = 0; q < 4; q++) {
                    float2 w01 = unpack2(wq[q].x), w23 = unpack2(wq[q].y);
                    float wsc = (jj == 0) ? w01.x : (jj == 1) ? w01.y : (jj == 2) ? w23.x : w23.y;
                    ull wp = pack2(wsc, wsc);
                    acc2[q][0] = fma2(wp, v01, acc2[q][0]);
                    acc2[q][1] = fma2(wp, v23, acc2[q][1]);
                }
            }
        }

        asm volatile("cp.async.wait_group 0;");
        __syncthreads();   // single per-tile barrier
    }

    // ---- write per-segment partials ----
    if ((lane & 7) == 0) {
        #pragma unroll
        for (int q = 0; q < 4; q++) {
            float2 sp = unpack2(sum2[q]);
            int qg = q0 + qb4 + q;
            g_s2[(seg * N_Q + qg) * HEADS + h2] = sp.x + sp.y;
        }
    }
    float4* acc4 = (float4*)g_acc;
    #pragma unroll
    for (int q = 0; q < 4; q++) {
        int qg = q0 + qb4 + q;
        float2 a0 = unpack2(acc2[q][0]);
        float2 a1 = unpack2(acc2[q][1]);
        float4 r; r.x = a0.x; r.y = a0.y; r.z = a1.x; r.w = a1.y;
        acc4[(size_t)(seg * N_Q + qg) * 32 + lane] = r;
    }
}

// ---------------- kernel 3: combine segment partials (plain sum / divide) ----------------
__global__ void combine_kernel(float* __restrict__ out) {
    int idx = blockIdx.x * 256 + threadIdx.x;
    int q = idx >> 5, lq = idx & 31, h = lq >> 3;
    const float4* acc4 = (const float4*)g_acc;
    float S = 0.0f;
    float4 A; A.x = A.y = A.z = A.w = 0.0f;
    #pragma unroll
    for (int s = 0; s < SEGS; s++) {
        S += g_s2[(s * N_Q + q) * HEADS + h];
        float4 a = acc4[(size_t)(s * N_Q + q) * 32 + lq];
        A.x += a.x; A.y += a.y; A.z += a.z; A.w += a.w;
    }
    float inv = 1.0f / S;
    float4 r; r.x = A.x * inv; r.y = A.y * inv; r.z = A.z * inv; r.w = A.w * inv;
    ((float4*)out)[idx] = r;
}

// ---------------- launch ----------------
extern "C" void kernel_launch(void* const* d_in, const int* in_sizes, int n_in,
                              void* d_out, int out_size) {
    const float* h_obs      = (const float*)d_in[0];
    const float* pos_obs    = (const float*)d_in[1];
    const float* pos_query  = (const float*)d_in[2];
    const int*   obs_batch  = (const int*)d_in[3];
    const int*   query_batch= (const int*)d_in[4];
    const float* W1         = (const float*)d_in[5];
    const float* b1         = (const float*)d_in[6];
    const float* W2         = (const float*)d_in[7];
    const float* ln_gamma   = (const float*)d_in[9];
    const float* ln_beta    = (const float*)d_in[10];
    const float* Wv         = (const float*)d_in[11];
    const float* bv         = (const float*)d_in[12];
    float* out = (float*)d_out;

    cudaFuncSetAttribute(fused_kernel, cudaFuncAttributeMaxDynamicSharedMemorySize, DYN_BYTES);

    pre_kernel<<<576, 128>>>(h_obs, pos_obs, pos_query, W1, b1, ln_gamma, ln_beta, Wv, bv);
    fused_kernel<<<dim3(N_Q / 32, SEGS), 256, DYN_BYTES>>>(
        pos_query, pos_obs, query_batch, obs_batch, W1, W2);
    combine_kernel<<<(N_Q * 32) / 256, 256>>>(out);
}